// round 15
// baseline (speedup 1.0000x reference)
#include <cuda_runtime.h>
#include <math.h>

// ---------------------------------------------------------------------------
// RotatedIoULoss — separable Green's-theorem clipping, software-pipelined
// grid-stride loop: prefetch next pair's data (11 float2 loads) into
// registers while computing the current pair, overlapping DRAM latency
// with the ~500-cycle compute chain. 2 adjacent boxes per iteration.
// ---------------------------------------------------------------------------

#define IOU_EPS 1e-6f
#define BLOCK 128
#define GRIDB 888          // 148 SMs * 6 blocks
#define MAXB  8192

__device__ float g_partial[MAXB];
__device__ unsigned int g_count = 0;   // reset by last block each launch

__device__ __forceinline__ float clampab(float v, float h) {
    return fminf(fmaxf(v, -h), h);
}

// loss for one pred/target box pair packed as 5+5 float2 + weights
__device__ __forceinline__ float pair_loss(
    float2 a0, float2 a1, float2 a2, float2 a3, float2 a4,
    float2 b0, float2 b1, float2 b2, float2 b3, float2 b4,
    float2 ww) {
    float loss = 0.f;
#pragma unroll
    for (int k = 0; k < 2; k++) {
        float px, py, pw, ph, pa, qx, qy, qw, qh, qa, w;
        if (k == 0) {
            px = a0.x; py = a0.y; pw = a1.x; ph = a1.y; pa = a2.x;
            qx = b0.x; qy = b0.y; qw = b1.x; qh = b1.y; qa = b2.x;
            w = ww.x;
        } else {
            px = a2.y; py = a3.x; pw = a3.y; ph = a4.x; pa = a4.y;
            qx = b2.y; qy = b3.x; qw = b3.y; qh = b4.x; qa = b4.y;
            w = ww.y;
        }

        // frame change into box2's local axes
        float cb, sb; __sincosf(qa, &sb, &cb);
        float dxc = px - qx, dyc = py - qy;
        float ox =  dxc * cb + dyc * sb;
        float oy = -dxc * sb + dyc * cb;
        float cr, sr; __sincosf(pa - qa, &sr, &cr);

        float hw = 0.5f * qw, hh = 0.5f * qh;
        float hx = 0.5f * pw, hy = 0.5f * ph;

        float ux = hx * cr,  uy = hx * sr;
        float wx = -hy * sr, wy = hy * cr;

        float v0x = ox + ux + wx, v0y = oy + uy + wy;
        float v1x = ox - ux + wx, v1y = oy - uy + wy;
        float v2x = ox - ux - wx, v2y = oy - uy - wy;
        float v3x = ox + ux - wx, v3y = oy + uy - wy;

        float dAx = 2.f * wx, dAy = 2.f * wy;
        float dBx = -2.f * ux, dBy = -2.f * uy;
        float iAx = __fdividef(1.f, dAx), iAy = __fdividef(1.f, dAy);
        float iBx = __fdividef(1.f, dBx), iBy = __fdividef(1.f, dBy);

        float area2 = 0.f;

#define EDGE(axv, ayv, dx_, dy_, ix_, iy_) do {                        \
            float ta = fmaf((axv), -(ix_), -hw * (ix_));               \
            float tb = fmaf((axv), -(ix_),  hw * (ix_));               \
            float tc = fmaf((ayv), -(iy_), -hh * (iy_));               \
            float td = fmaf((ayv), -(iy_),  hh * (iy_));               \
            float a_ = __saturatef(fminf(tc, td));                     \
            float b_ = __saturatef(fmaxf(tc, td));                     \
            float t1 = fminf(ta, tb), t2 = fmaxf(ta, tb);              \
            float c1 = fminf(fmaxf(t1, a_), b_);                       \
            float c2 = fminf(fmaxf(t2, a_), b_);                       \
            float Xa = clampab(fmaf(a_, (dx_), (axv)), hw);            \
            float X1 = clampab(fmaf(c1, (dx_), (axv)), hw);            \
            float X2 = clampab(fmaf(c2, (dx_), (axv)), hw);            \
            float Xb = clampab(fmaf(b_, (dx_), (axv)), hw);            \
            float e = Xa * (c1 - a_);                                  \
            e = fmaf(X1, c2 - a_, e);                                  \
            e = fmaf(X2, b_ - c1, e);                                  \
            e = fmaf(Xb, b_ - c2, e);                                  \
            area2 = fmaf((dy_), e, area2);                             \
        } while (0)

        EDGE(v3x, v3y,  dAx,  dAy,  iAx,  iAy);
        EDGE(v0x, v0y,  dBx,  dBy,  iBx,  iBy);
        EDGE(v1x, v1y, -dAx, -dAy, -iAx, -iAy);
        EDGE(v2x, v2y, -dBx, -dBy, -iBx, -iBy);
#undef EDGE

        float inter = 0.5f * fabsf(area2);

        float radx = fabsf(ux) + fabsf(wx);
        float rady = fabsf(uy) + fabsf(wy);
        bool sep = (fabsf(ox) > hw + radx) || (fabsf(oy) > hh + rady);
        inter = sep ? 0.f : inter;

        float a1 = pw * ph, a2 = qw * qh;
        float iou = __fdividef(inter, a1 + a2 - inter);
        iou = fmaxf(iou, IOU_EPS);
        loss += -__logf(iou) * w;
    }
    return loss;
}

__global__ void __launch_bounds__(BLOCK, 6)
rl_main(const float* __restrict__ pred,
        const float* __restrict__ target,
        const float* __restrict__ weight,
        float* __restrict__ out,
        int n, int nb, float inv_n) {
    const float2* pv = (const float2*)pred;
    const float2* tv = (const float2*)target;
    const float2* wv = (const float2*)weight;

    int tid0 = blockIdx.x * BLOCK + threadIdx.x;
    int stride = gridDim.x * BLOCK;
    int npairs = n >> 1;

    float loss = 0.f;

    int p = tid0;
    if (p < npairs) {
        // preload first pair
        size_t o = (size_t)p * 5;
        float2 a0 = pv[o], a1 = pv[o+1], a2 = pv[o+2], a3 = pv[o+3], a4 = pv[o+4];
        float2 b0 = tv[o], b1 = tv[o+1], b2 = tv[o+2], b3 = tv[o+3], b4 = tv[o+4];
        float2 ww = wv[p];

        while (true) {
            int pn = p + stride;
            bool more = pn < npairs;
            int pc = more ? pn : p;           // clamped prefetch index (safe)
            size_t oc = (size_t)pc * 5;
            // prefetch next pair's data (overlaps with compute below)
            float2 na0 = pv[oc],   na1 = pv[oc+1], na2 = pv[oc+2];
            float2 na3 = pv[oc+3], na4 = pv[oc+4];
            float2 nb0 = tv[oc],   nb1 = tv[oc+1], nb2 = tv[oc+2];
            float2 nb3 = tv[oc+3], nb4 = tv[oc+4];
            float2 nww = wv[pc];

            loss += pair_loss(a0, a1, a2, a3, a4,
                              b0, b1, b2, b3, b4, ww);

            if (!more) break;
            a0 = na0; a1 = na1; a2 = na2; a3 = na3; a4 = na4;
            b0 = nb0; b1 = nb1; b2 = nb2; b3 = nb3; b4 = nb4;
            ww = nww;
            p = pn;
        }
    }

    // odd-n tail: one scalar box handled by thread 0 of block 0
    if ((n & 1) && tid0 == 0) {
        int i = n - 1;
        const float* P = pred + (size_t)i * 5;
        const float* T = target + (size_t)i * 5;
        float2 a0 = make_float2(P[0], P[1]);
        float2 a1 = make_float2(P[2], P[3]);
        float2 a2 = make_float2(P[4], 0.f);
        float2 a3 = make_float2(0.f, 1.f);
        float2 a4 = make_float2(1.f, 0.f);
        float2 b0 = make_float2(T[0], T[1]);
        float2 b1 = make_float2(T[2], T[3]);
        float2 b2 = make_float2(T[4], 0.f);
        float2 b3 = make_float2(0.f, 1.f);
        float2 b4 = make_float2(1.f, 0.f);
        float2 ww = make_float2(weight[i], 0.f);
        loss += pair_loss(a0, a1, a2, a3, a4, b0, b1, b2, b3, b4, ww);
    }

    // ---- block reduction -> per-block partial ----
    unsigned mask = 0xFFFFFFFFu;
#pragma unroll
    for (int o = 16; o > 0; o >>= 1)
        loss += __shfl_down_sync(mask, loss, o);

    __shared__ float ws[BLOCK / 32];
    int lane = threadIdx.x & 31;
    int wid = threadIdx.x >> 5;
    if (lane == 0) ws[wid] = loss;
    __syncthreads();
    __shared__ bool is_last;
    if (threadIdx.x == 0) {
        float v = 0.f;
#pragma unroll
        for (int w = 0; w < BLOCK / 32; w++) v += ws[w];
        g_partial[blockIdx.x] = v;
        __threadfence();
        unsigned prev = atomicAdd(&g_count, 1u);
        is_last = (prev == (unsigned)(nb - 1));
    }
    __syncthreads();

    // ---- last block: final reduction (deterministic) ----
    if (is_last) {
        double s = 0.0;
        for (int j = threadIdx.x; j < nb; j += BLOCK)
            s += (double)g_partial[j];
#pragma unroll
        for (int o = 16; o > 0; o >>= 1)
            s += __shfl_down_sync(mask, s, o);
        __shared__ double ds[BLOCK / 32];
        if (lane == 0) ds[wid] = s;
        __syncthreads();
        if (threadIdx.x == 0) {
            double v = 0.0;
#pragma unroll
            for (int w = 0; w < BLOCK / 32; w++) v += ds[w];
            out[0] = (float)(v * (double)inv_n);
            g_count = 0;  // reset for next graph replay
        }
    }
}

extern "C" void kernel_launch(void* const* d_in, const int* in_sizes, int n_in,
                              void* d_out, int out_size) {
    const float* pred   = (const float*)d_in[0];
    const float* target = (const float*)d_in[1];
    const float* weight = (const float*)d_in[2];
    float* out = (float*)d_out;
    int n = in_sizes[2];

    int npairs = n >> 1;
    int grid = (npairs + BLOCK - 1) / BLOCK;
    if (grid > GRIDB) grid = GRIDB;   // persistent-style: 6 blocks/SM
    if (grid < 1) grid = 1;
    rl_main<<<grid, BLOCK>>>(pred, target, weight, out, n, grid,
                             1.0f / (float)n);
}

// round 17
// speedup vs baseline: 1.4848x; 1.4848x over previous
#include <cuda_runtime.h>
#include <math.h>

// ---------------------------------------------------------------------------
// RotatedIoULoss — closed-form Green's-theorem clipping.
// 2 adjacent boxes per thread (float2 loads, no smem staging).
//
// Box1 in box2's frame; box2 = [-hw,hw] x [-hh,hh].
// area(P ∩ box) = ∮ clampx(x) d(clampy(y)). Per edge (affine, param t):
//   contribution = dy * ∫_{[a,b]} clampx(x(t)) dt,   [a,b] = y-slab window
//                = (dy/dx) * [G(x(b)) - G(x(a))]
// with antiderivative 2G(u) = min(u^2, hw^2) + 2hw*max(|u|-hw, 0).
// Accumulator holds Σ slope*(2G diff) = 2*area  ->  inter = 0.5*|area2|.
// (Note: ∮ x dy = area directly; no extra shoelace 1/2.)
// Opposite edges share the slope dy/dx (2 divides per box). Degenerate
// cases: dy=0 -> slope=0 kills the term; dx=0 -> Gdiff=0 exactly and the
// +/-inf slope is clamped to +/-1e30 (1e30*0=0).
// ---------------------------------------------------------------------------

#define IOU_EPS 1e-6f
#define BLOCK 128
#define MAXB  8192

__device__ float g_partial[MAXB];
__device__ unsigned int g_count = 0;   // reset by last block each launch

__device__ __forceinline__ float box_loss(
    float px, float py, float pw, float ph, float pa,
    float qx, float qy, float qw, float qh, float qa, float w) {

    // frame change into box2's local axes
    float cb, sb; __sincosf(qa, &sb, &cb);
    float dxc = px - qx, dyc = py - qy;
    float ox =  dxc * cb + dyc * sb;
    float oy = -dxc * sb + dyc * cb;
    float cr, sr; __sincosf(pa - qa, &sr, &cr);

    float hw = 0.5f * qw, hh = 0.5f * qh;
    float hx = 0.5f * pw, hy = 0.5f * ph;

    float ux = hx * cr,  uy = hx * sr;
    float wx = -hy * sr, wy = hy * cr;

    // corners (CCW)
    float v0x = ox + ux + wx, v0y = oy + uy + wy;
    float v1x = ox - ux + wx, v1y = oy - uy + wy;
    float v2x = ox - ux - wx, v2y = oy - uy - wy;
    float v3x = ox + ux - wx, v3y = oy + uy - wy;

    // edge dirs: A = v3->v0 = 2w, B = v0->v1 = -2u (C=-A, D=-B)
    float dAx = wx + wx, dAy = wy + wy;
    float dBx = -(ux + ux), dBy = -(uy + uy);
    float iAy = __fdividef(1.f, dAy);
    float iBy = __fdividef(1.f, dBy);
    const float BIG = 1e30f;
    float slA = fminf(fmaxf(__fdividef(dAy, dAx), -BIG), BIG);
    float slB = fminf(fmaxf(__fdividef(dBy, dBx), -BIG), BIG);
    float hhiA = hh * iAy, hhiB = hh * iBy;
    float hw2 = hw * hw;
    float hw2x = hw + hw;

    float area2 = 0.f;   // accumulates sum of slope * (2G) differences

#define EDGE(axv, ayv, dx_, iy_, hhi_, sl_) do {                       \
        float tc = fmaf((ayv), -(iy_), -(hhi_));                       \
        float td = fmaf((ayv), -(iy_),  (hhi_));                       \
        float a_ = __saturatef(fminf(tc, td));                         \
        float b_ = __saturatef(fmaxf(tc, td));                         \
        float xa = fmaf(a_, (dx_), (axv));                             \
        float xb = fmaf(b_, (dx_), (axv));                             \
        float Fa = fmaf(hw2x, fmaxf(fabsf(xa) - hw, 0.f),              \
                        fminf(xa * xa, hw2));                          \
        float Fb = fmaf(hw2x, fmaxf(fabsf(xb) - hw, 0.f),              \
                        fminf(xb * xb, hw2));                          \
        area2 = fmaf((sl_), Fb - Fa, area2);                           \
    } while (0)

    EDGE(v3x, v3y,  dAx,  iAy,  hhiA, slA);   // v3->v0
    EDGE(v0x, v0y,  dBx,  iBy,  hhiB, slB);   // v0->v1
    EDGE(v1x, v1y, -dAx, -iAy, -hhiA, slA);   // v1->v2 (dir = -A, same slope)
    EDGE(v2x, v2y, -dBx, -iBy, -hhiB, slB);   // v2->v3 (dir = -B, same slope)
#undef EDGE

    // area2 = 2*area (G carries factor 2); |.| handles orientation
    float inter = 0.5f * fabsf(area2);

    // conservative separation: certain-disjoint -> exact zero (predicated)
    float radx = fabsf(ux) + fabsf(wx);
    float rady = fabsf(uy) + fabsf(wy);
    bool sep = (fabsf(ox) > hw + radx) || (fabsf(oy) > hh + rady);
    inter = sep ? 0.f : inter;

    float a1 = pw * ph, a2 = qw * qh;
    float iou = fmaxf(__fdividef(inter, a1 + a2 - inter), IOU_EPS);
    return -__logf(iou) * w;
}

__global__ void __launch_bounds__(BLOCK, 10)
rl_main(const float* __restrict__ pred,
        const float* __restrict__ target,
        const float* __restrict__ weight,
        float* __restrict__ out,
        int n, int nb, float inv_n) {
    int Tid = blockIdx.x * BLOCK + threadIdx.x;   // pair index
    int i0 = 2 * Tid;

    // benign defaults: iou=1, weight 0 -> 0 loss
    float p0x = 0.f, p0y = 0.f, p0w = 1.f, p0h = 1.f, p0a = 0.f;
    float p1x = 0.f, p1y = 0.f, p1w = 1.f, p1h = 1.f, p1a = 0.f;
    float q0x = 0.f, q0y = 0.f, q0w = 1.f, q0h = 1.f, q0a = 0.f;
    float q1x = 0.f, q1y = 0.f, q1w = 1.f, q1h = 1.f, q1a = 0.f;
    float w0 = 0.f, w1 = 0.f;

    if (i0 + 1 < n) {
        const float2* p2 = (const float2*)(pred)   + (size_t)Tid * 5;
        const float2* t2 = (const float2*)(target) + (size_t)Tid * 5;
        float2 a0 = p2[0], a1 = p2[1], a2 = p2[2], a3 = p2[3], a4 = p2[4];
        float2 b0 = t2[0], b1 = t2[1], b2 = t2[2], b3 = t2[3], b4 = t2[4];
        float2 ww = ((const float2*)weight)[Tid];
        p0x = a0.x; p0y = a0.y; p0w = a1.x; p0h = a1.y; p0a = a2.x;
        p1x = a2.y; p1y = a3.x; p1w = a3.y; p1h = a4.x; p1a = a4.y;
        q0x = b0.x; q0y = b0.y; q0w = b1.x; q0h = b1.y; q0a = b2.x;
        q1x = b2.y; q1y = b3.x; q1w = b3.y; q1h = b4.x; q1a = b4.y;
        w0 = ww.x; w1 = ww.y;
    } else if (i0 < n) {
        const float* P = pred + (size_t)i0 * 5;
        const float* T = target + (size_t)i0 * 5;
        p0x = P[0]; p0y = P[1]; p0w = P[2]; p0h = P[3]; p0a = P[4];
        q0x = T[0]; q0y = T[1]; q0w = T[2]; q0h = T[3]; q0a = T[4];
        w0 = weight[i0];
    }

    // two independent chains, fully interleavable
    float loss = box_loss(p0x, p0y, p0w, p0h, p0a,
                          q0x, q0y, q0w, q0h, q0a, w0)
               + box_loss(p1x, p1y, p1w, p1h, p1a,
                          q1x, q1y, q1w, q1h, q1a, w1);

    // ---- block reduction -> per-block partial ----
    unsigned mask = 0xFFFFFFFFu;
#pragma unroll
    for (int o = 16; o > 0; o >>= 1)
        loss += __shfl_down_sync(mask, loss, o);

    __shared__ float ws[BLOCK / 32];
    int lane = threadIdx.x & 31;
    int wid = threadIdx.x >> 5;
    if (lane == 0) ws[wid] = loss;
    __syncthreads();
    __shared__ bool is_last;
    if (threadIdx.x == 0) {
        float v = 0.f;
#pragma unroll
        for (int w = 0; w < BLOCK / 32; w++) v += ws[w];
        g_partial[blockIdx.x] = v;
        __threadfence();
        unsigned prev = atomicAdd(&g_count, 1u);
        is_last = (prev == (unsigned)(nb - 1));
    }
    __syncthreads();

    // ---- last block: final reduction (deterministic) ----
    if (is_last) {
        double s = 0.0;
        for (int j = threadIdx.x; j < nb; j += BLOCK)
            s += (double)g_partial[j];
#pragma unroll
        for (int o = 16; o > 0; o >>= 1)
            s += __shfl_down_sync(mask, s, o);
        __shared__ double ds[BLOCK / 32];
        if (lane == 0) ds[wid] = s;
        __syncthreads();
        if (threadIdx.x == 0) {
            double v = 0.0;
#pragma unroll
            for (int w = 0; w < BLOCK / 32; w++) v += ds[w];
            out[0] = (float)(v * (double)inv_n);
            g_count = 0;  // reset for next graph replay
        }
    }
}

extern "C" void kernel_launch(void* const* d_in, const int* in_sizes, int n_in,
                              void* d_out, int out_size) {
    const float* pred   = (const float*)d_in[0];
    const float* target = (const float*)d_in[1];
    const float* weight = (const float*)d_in[2];
    float* out = (float*)d_out;
    int n = in_sizes[2];

    int pairs = (n + 1) / 2;
    int grid = (pairs + BLOCK - 1) / BLOCK;
    if (grid > MAXB) grid = MAXB;  // n = 1e6 -> 3907 blocks
    rl_main<<<grid, BLOCK>>>(pred, target, weight, out, n, grid,
                             1.0f / (float)n);
}